// round 1
// baseline (speedup 1.0000x reference)
#include <cuda_runtime.h>
#include <math.h>

#define E_   1024
#define NH_  8
#define HD_  128
#define BS_  2048

// ---- scratch (device globals: no allocation allowed) ----
__device__ float g_Q[BS_ * E_];
__device__ float g_K[BS_ * E_];
__device__ float g_V[BS_ * E_];
__device__ float g_P[(size_t)NH_ * BS_ * BS_];   // 8 x 2048 x 2048 probs (head-major planes)
__device__ float g_attn[BS_ * E_];
__device__ float g_h[BS_ * E_];
__device__ float g_f1[BS_ * 4 * E_];
__device__ float g_f2[BS_ * E_];

// ============================================================
// Generic NT GEMM: C[M,N] = A[M,K] @ W[N,K]^T + bias, opt ReLU
// BM=BN=64, BK=16, 256 threads, 4x4 micro-tile per thread.
// Grid: (N/64, M/64)
// ============================================================
__global__ __launch_bounds__(256) void gemm_nt(
    const float* __restrict__ A, const float* __restrict__ W,
    const float* __restrict__ bias, float* __restrict__ C,
    int N, int K, int relu)
{
    __shared__ float As[16][64];
    __shared__ float Bs[16][64];
    const int bm = blockIdx.y * 64;
    const int bn = blockIdx.x * 64;
    const int tid = threadIdx.x;
    const int lr = tid >> 2;          // 0..63
    const int lc = (tid & 3) << 2;    // 0,4,8,12
    const int tm = (tid >> 4) << 2;   // 0..60
    const int tn = (tid & 15) << 2;   // 0..60

    float acc[4][4] = {};

    for (int k0 = 0; k0 < K; k0 += 16) {
        float4 a = *(const float4*)(A + (size_t)(bm + lr) * K + k0 + lc);
        float4 b = *(const float4*)(W + (size_t)(bn + lr) * K + k0 + lc);
        __syncthreads();
        As[lc + 0][lr] = a.x; As[lc + 1][lr] = a.y;
        As[lc + 2][lr] = a.z; As[lc + 3][lr] = a.w;
        Bs[lc + 0][lr] = b.x; Bs[lc + 1][lr] = b.y;
        Bs[lc + 2][lr] = b.z; Bs[lc + 3][lr] = b.w;
        __syncthreads();
#pragma unroll
        for (int k = 0; k < 16; ++k) {
            float4 av = *(const float4*)&As[k][tm];
            float4 bv = *(const float4*)&Bs[k][tn];
            float am[4] = {av.x, av.y, av.z, av.w};
            float bw[4] = {bv.x, bv.y, bv.z, bv.w};
#pragma unroll
            for (int i = 0; i < 4; ++i)
#pragma unroll
                for (int j = 0; j < 4; ++j)
                    acc[i][j] = fmaf(am[i], bw[j], acc[i][j]);
        }
    }

#pragma unroll
    for (int i = 0; i < 4; ++i) {
        const int row = bm + tm + i;
#pragma unroll
        for (int j = 0; j < 4; ++j) {
            const int col = bn + tn + j;
            float v = acc[i][j] + bias[col];
            if (relu) v = fmaxf(v, 0.0f);
            C[(size_t)row * N + col] = v;
        }
    }
}

// ============================================================
// Scores + softmax-over-heads.
// s[n,m,h] = scale * sum_d Q[n, h*128+d] * K[m, h*128+d]
// probs = softmax over h (8 values), stored as P[h][n][m].
// Tile 32(n) x 32(m), 256 threads, 2x2 per thread, loop heads.
// Grid: (2048/32, 2048/32)
// ============================================================
__global__ __launch_bounds__(256) void scores_kernel(
    const float* __restrict__ Q, const float* __restrict__ Kmat,
    float* __restrict__ P)
{
    __shared__ float Qs[16][32];
    __shared__ float Ks[16][32];
    const int n0 = blockIdx.y * 32;
    const int m0 = blockIdx.x * 32;
    const int tid = threadIdx.x;
    const int lr = tid >> 3;          // 0..31
    const int lc = (tid & 7) << 1;    // 0..14
    const int tm = (tid >> 4) << 1;   // 0..30 (n sub)
    const int tn = (tid & 15) << 1;   // 0..30 (m sub)

    float acc[8][2][2];

#pragma unroll
    for (int h = 0; h < 8; ++h) {
        float c00 = 0.f, c01 = 0.f, c10 = 0.f, c11 = 0.f;
        for (int kt = 0; kt < 128; kt += 16) {
            const int k0 = h * 128 + kt;
            float2 a = *(const float2*)(Q    + (size_t)(n0 + lr) * 1024 + k0 + lc);
            float2 b = *(const float2*)(Kmat + (size_t)(m0 + lr) * 1024 + k0 + lc);
            __syncthreads();
            Qs[lc][lr] = a.x; Qs[lc + 1][lr] = a.y;
            Ks[lc][lr] = b.x; Ks[lc + 1][lr] = b.y;
            __syncthreads();
#pragma unroll
            for (int k = 0; k < 16; ++k) {
                float a0 = Qs[k][tm], a1 = Qs[k][tm + 1];
                float b0 = Ks[k][tn], b1 = Ks[k][tn + 1];
                c00 = fmaf(a0, b0, c00);
                c01 = fmaf(a0, b1, c01);
                c10 = fmaf(a1, b0, c10);
                c11 = fmaf(a1, b1, c11);
            }
        }
        acc[h][0][0] = c00; acc[h][0][1] = c01;
        acc[h][1][0] = c10; acc[h][1][1] = c11;
    }

    const float scale = 0.08838834764831845f;  // 1/sqrt(128)
#pragma unroll
    for (int i = 0; i < 2; ++i)
#pragma unroll
        for (int j = 0; j < 2; ++j) {
            float s[8], mx = -1e30f;
#pragma unroll
            for (int h = 0; h < 8; ++h) { s[h] = acc[h][i][j] * scale; mx = fmaxf(mx, s[h]); }
            float sum = 0.f;
#pragma unroll
            for (int h = 0; h < 8; ++h) { s[h] = expf(s[h] - mx); sum += s[h]; }
            const float inv = 1.0f / sum;
            const size_t base = (size_t)(n0 + tm + i) * 2048 + (m0 + tn + j);
#pragma unroll
            for (int h = 0; h < 8; ++h)
                P[((size_t)h << 22) + base] = s[h] * inv;
        }
}

// ============================================================
// Per-head attention GEMM (NN):
//   attn[n, h*128+d] = sum_m P_h[n][m] * V[m, h*128+d]
// M=2048, N=128 per head, K=2048. Grid: (128/64, 2048/64, 8)
// ============================================================
__global__ __launch_bounds__(256) void attn_gemm(
    const float* __restrict__ P, const float* __restrict__ V,
    float* __restrict__ C)
{
    const int h = blockIdx.z;
    const float* A  = P + ((size_t)h << 22);
    const float* B  = V + h * 128;
    float*       Cc = C + h * 128;

    __shared__ float As[16][64];
    __shared__ float Bs[16][64];
    const int bm = blockIdx.y * 64;
    const int bn = blockIdx.x * 64;
    const int tid = threadIdx.x;
    const int lrA = tid >> 2;         // 0..63
    const int lcA = (tid & 3) << 2;   // 0,4,8,12
    const int krB = tid >> 4;         // 0..15
    const int cB  = (tid & 15) << 2;  // 0..60
    const int tm = (tid >> 4) << 2;
    const int tn = (tid & 15) << 2;

    float acc[4][4] = {};

    for (int k0 = 0; k0 < 2048; k0 += 16) {
        float4 a = *(const float4*)(A + (size_t)(bm + lrA) * 2048 + k0 + lcA);
        float4 b = *(const float4*)(B + (size_t)(k0 + krB) * 1024 + bn + cB);
        __syncthreads();
        As[lcA + 0][lrA] = a.x; As[lcA + 1][lrA] = a.y;
        As[lcA + 2][lrA] = a.z; As[lcA + 3][lrA] = a.w;
        *(float4*)&Bs[krB][cB] = b;
        __syncthreads();
#pragma unroll
        for (int k = 0; k < 16; ++k) {
            float4 av = *(const float4*)&As[k][tm];
            float4 bv = *(const float4*)&Bs[k][tn];
            float am[4] = {av.x, av.y, av.z, av.w};
            float bw[4] = {bv.x, bv.y, bv.z, bv.w};
#pragma unroll
            for (int i = 0; i < 4; ++i)
#pragma unroll
                for (int j = 0; j < 4; ++j)
                    acc[i][j] = fmaf(am[i], bw[j], acc[i][j]);
        }
    }

#pragma unroll
    for (int i = 0; i < 4; ++i)
#pragma unroll
        for (int j = 0; j < 4; ++j)
            Cc[(size_t)(bm + tm + i) * 1024 + bn + tn + j] = acc[i][j];
}

// ============================================================
// Residual + LayerNorm: Y = LN(X + R) * g + b, row length 1024.
// 256 threads, float4 per thread. Grid: 2048.
// ============================================================
__global__ __launch_bounds__(256) void resid_ln(
    const float* __restrict__ X, const float* __restrict__ R,
    const float* __restrict__ g, const float* __restrict__ b,
    float* __restrict__ Y)
{
    __shared__ float red[8];
    const int row = blockIdx.x;
    const int tid = threadIdx.x;

    float4 xv = ((const float4*)(X + (size_t)row * 1024))[tid];
    float4 rv = ((const float4*)(R + (size_t)row * 1024))[tid];
    float v[4] = {xv.x + rv.x, xv.y + rv.y, xv.z + rv.z, xv.w + rv.w};

    float s = v[0] + v[1] + v[2] + v[3];
#pragma unroll
    for (int o = 16; o; o >>= 1) s += __shfl_xor_sync(0xffffffffu, s, o);
    if ((tid & 31) == 0) red[tid >> 5] = s;
    __syncthreads();
    float mean = 0.f;
#pragma unroll
    for (int w = 0; w < 8; ++w) mean += red[w];
    mean *= (1.0f / 1024.0f);

    float d0 = v[0] - mean, d1 = v[1] - mean, d2 = v[2] - mean, d3 = v[3] - mean;
    float ss = d0 * d0 + d1 * d1 + d2 * d2 + d3 * d3;
#pragma unroll
    for (int o = 16; o; o >>= 1) ss += __shfl_xor_sync(0xffffffffu, ss, o);
    __syncthreads();
    if ((tid & 31) == 0) red[tid >> 5] = ss;
    __syncthreads();
    float var = 0.f;
#pragma unroll
    for (int w = 0; w < 8; ++w) var += red[w];
    var *= (1.0f / 1024.0f);
    const float rstd = rsqrtf(var + 1e-5f);

    float4 gv = ((const float4*)g)[tid];
    float4 bv = ((const float4*)b)[tid];
    float4 o4;
    o4.x = d0 * rstd * gv.x + bv.x;
    o4.y = d1 * rstd * gv.y + bv.y;
    o4.z = d2 * rstd * gv.z + bv.z;
    o4.w = d3 * rstd * gv.w + bv.w;
    ((float4*)(Y + (size_t)row * 1024))[tid] = o4;
}

// ============================================================
extern "C" void kernel_launch(void* const* d_in, const int* in_sizes, int n_in,
                              void* d_out, int out_size)
{
    (void)in_sizes; (void)n_in; (void)out_size;
    const float* x1  = (const float*)d_in[0];
    const float* x2  = (const float*)d_in[1];
    const float* Wq  = (const float*)d_in[2];
    const float* bq  = (const float*)d_in[3];
    const float* Wk  = (const float*)d_in[4];
    const float* bk  = (const float*)d_in[5];
    const float* Wv  = (const float*)d_in[6];
    const float* bv  = (const float*)d_in[7];
    const float* Wo  = (const float*)d_in[8];
    const float* bo  = (const float*)d_in[9];
    const float* W1  = (const float*)d_in[10];
    const float* b1  = (const float*)d_in[11];
    const float* W2  = (const float*)d_in[12];
    const float* b2  = (const float*)d_in[13];
    const float* g1  = (const float*)d_in[14];
    const float* be1 = (const float*)d_in[15];
    const float* g2  = (const float*)d_in[16];
    const float* be2 = (const float*)d_in[17];
    float* out = (float*)d_out;

    float *Q, *K, *V, *P, *attn, *hb, *f1, *f2;
    cudaGetSymbolAddress((void**)&Q,    g_Q);
    cudaGetSymbolAddress((void**)&K,    g_K);
    cudaGetSymbolAddress((void**)&V,    g_V);
    cudaGetSymbolAddress((void**)&P,    g_P);
    cudaGetSymbolAddress((void**)&attn, g_attn);
    cudaGetSymbolAddress((void**)&hb,   g_h);
    cudaGetSymbolAddress((void**)&f1,   g_f1);
    cudaGetSymbolAddress((void**)&f2,   g_f2);

    dim3 t(256);

    // QKV projections
    gemm_nt<<<dim3(16, 32), t>>>(x1, Wq, bq, Q, 1024, 1024, 0);
    gemm_nt<<<dim3(16, 32), t>>>(x2, Wk, bk, K, 1024, 1024, 0);
    gemm_nt<<<dim3(16, 32), t>>>(x2, Wv, bv, V, 1024, 1024, 0);

    // scores + softmax over heads -> P
    scores_kernel<<<dim3(64, 64), t>>>(Q, K, P);

    // attn = P_h @ V_h per head
    attn_gemm<<<dim3(2, 32, 8), t>>>(P, V, attn);

    // output projection (into f2 as temp)
    gemm_nt<<<dim3(16, 32), t>>>(attn, Wo, bo, f2, 1024, 1024, 0);

    // h = LN(x1 + attnproj)
    resid_ln<<<2048, t>>>(f2, x1, g1, be1, hb);

    // FFN
    gemm_nt<<<dim3(64, 32), t>>>(hb, W1, b1, f1, 4096, 1024, 1);
    gemm_nt<<<dim3(16, 32), t>>>(f1, W2, b2, f2, 1024, 4096, 0);

    // out = LN(h + ffn)
    resid_ln<<<2048, t>>>(f2, hb, g2, be2, out);
}

// round 2
// speedup vs baseline: 1.1748x; 1.1748x over previous
#include <cuda_runtime.h>
#include <math.h>

#define E_   1024
#define NH_  8
#define HD_  128
#define BS_  2048

// ---- scratch (device globals: no allocation allowed) ----
__device__ float g_Q[BS_ * E_];
__device__ float g_K[BS_ * E_];
__device__ float g_V[BS_ * E_];
__device__ float g_P[(size_t)NH_ * BS_ * BS_];   // 8 x 2048 x 2048 score/prob planes
__device__ float g_attn[BS_ * E_];
__device__ float g_h[BS_ * E_];
__device__ float g_f1[BS_ * 4 * E_];
__device__ float g_f2[BS_ * E_];

// ---- packed f32x2 helpers (SASS FFMA2; PTX-only path) ----
__device__ __forceinline__ unsigned long long fma2(unsigned long long a,
                                                   unsigned long long b,
                                                   unsigned long long c) {
    unsigned long long d;
    asm("fma.rn.f32x2 %0, %1, %2, %3;" : "=l"(d) : "l"(a), "l"(b), "l"(c));
    return d;
}
__device__ __forceinline__ unsigned long long dup2(float x) {
    unsigned long long d;
    asm("mov.b64 %0, {%1, %1};" : "=l"(d) : "f"(x));
    return d;
}
__device__ __forceinline__ void unpack2(unsigned long long p, float& lo, float& hi) {
    asm("mov.b64 {%0, %1}, %2;" : "=f"(lo), "=f"(hi) : "l"(p));
}

// ============================================================
// NT GEMM: C[M,N] = A[M,K] @ W[N,K]^T + bias, opt ReLU
// BM=BN=64, BK=16, 256 threads, 4x4 micro-tile, f32x2 FMA.
// Grid: (N/64, M/64)
// ============================================================
__global__ __launch_bounds__(256) void gemm_nt(
    const float* __restrict__ A, const float* __restrict__ W,
    const float* __restrict__ bias, float* __restrict__ C,
    int N, int K, int relu)
{
    __shared__ float As[16][64];
    __shared__ float Bs[16][64];
    const int bm = blockIdx.y * 64;
    const int bn = blockIdx.x * 64;
    const int tid = threadIdx.x;
    const int lr = tid >> 2;          // 0..63
    const int lc = (tid & 3) << 2;    // 0,4,8,12
    const int tm = (tid >> 4) << 2;   // 0..60
    const int tn = (tid & 15) << 2;   // 0..60

    unsigned long long acc[4][2];
#pragma unroll
    for (int i = 0; i < 4; ++i) { acc[i][0] = 0ull; acc[i][1] = 0ull; }

    for (int k0 = 0; k0 < K; k0 += 16) {
        float4 a = *(const float4*)(A + (size_t)(bm + lr) * K + k0 + lc);
        float4 b = *(const float4*)(W + (size_t)(bn + lr) * K + k0 + lc);
        __syncthreads();
        As[lc + 0][lr] = a.x; As[lc + 1][lr] = a.y;
        As[lc + 2][lr] = a.z; As[lc + 3][lr] = a.w;
        Bs[lc + 0][lr] = b.x; Bs[lc + 1][lr] = b.y;
        Bs[lc + 2][lr] = b.z; Bs[lc + 3][lr] = b.w;
        __syncthreads();
#pragma unroll
        for (int k = 0; k < 16; ++k) {
            float4 av = *(const float4*)&As[k][tm];
            const unsigned long long* bp = (const unsigned long long*)&Bs[k][tn];
            unsigned long long b0 = bp[0], b1 = bp[1];
            unsigned long long a0 = dup2(av.x), a1 = dup2(av.y);
            unsigned long long a2 = dup2(av.z), a3 = dup2(av.w);
            acc[0][0] = fma2(a0, b0, acc[0][0]); acc[0][1] = fma2(a0, b1, acc[0][1]);
            acc[1][0] = fma2(a1, b0, acc[1][0]); acc[1][1] = fma2(a1, b1, acc[1][1]);
            acc[2][0] = fma2(a2, b0, acc[2][0]); acc[2][1] = fma2(a2, b1, acc[2][1]);
            acc[3][0] = fma2(a3, b0, acc[3][0]); acc[3][1] = fma2(a3, b1, acc[3][1]);
        }
    }

#pragma unroll
    for (int i = 0; i < 4; ++i) {
        const int row = bm + tm + i;
        float c0, c1, c2, c3;
        unpack2(acc[i][0], c0, c1);
        unpack2(acc[i][1], c2, c3);
        float v0 = c0 + bias[bn + tn + 0];
        float v1 = c1 + bias[bn + tn + 1];
        float v2 = c2 + bias[bn + tn + 2];
        float v3 = c3 + bias[bn + tn + 3];
        if (relu) {
            v0 = fmaxf(v0, 0.f); v1 = fmaxf(v1, 0.f);
            v2 = fmaxf(v2, 0.f); v3 = fmaxf(v3, 0.f);
        }
        float4 o4 = {v0, v1, v2, v3};
        *(float4*)(C + (size_t)row * N + bn + tn) = o4;
    }
}

// ============================================================
// Per-head scores GEMM (NT): S_h[n,m] = sum_d Q[n,h*128+d]*K[m,h*128+d]
// Raw scores (scale folded into softmax). Grid: (32, 32, 8)
// ============================================================
__global__ __launch_bounds__(256) void scores_gemm(
    const float* __restrict__ Q, const float* __restrict__ Kmat,
    float* __restrict__ P)
{
    const int h = blockIdx.z;
    const float* A = Q    + h * 128;
    const float* B = Kmat + h * 128;
    float*       S = P + ((size_t)h << 22);

    __shared__ float As[16][64];
    __shared__ float Bs[16][64];
    const int bm = blockIdx.y * 64;
    const int bn = blockIdx.x * 64;
    const int tid = threadIdx.x;
    const int lr = tid >> 2;
    const int lc = (tid & 3) << 2;
    const int tm = (tid >> 4) << 2;
    const int tn = (tid & 15) << 2;

    unsigned long long acc[4][2];
#pragma unroll
    for (int i = 0; i < 4; ++i) { acc[i][0] = 0ull; acc[i][1] = 0ull; }

    for (int k0 = 0; k0 < 128; k0 += 16) {
        float4 a = *(const float4*)(A + (size_t)(bm + lr) * 1024 + k0 + lc);
        float4 b = *(const float4*)(B + (size_t)(bn + lr) * 1024 + k0 + lc);
        __syncthreads();
        As[lc + 0][lr] = a.x; As[lc + 1][lr] = a.y;
        As[lc + 2][lr] = a.z; As[lc + 3][lr] = a.w;
        Bs[lc + 0][lr] = b.x; Bs[lc + 1][lr] = b.y;
        Bs[lc + 2][lr] = b.z; Bs[lc + 3][lr] = b.w;
        __syncthreads();
#pragma unroll
        for (int k = 0; k < 16; ++k) {
            float4 av = *(const float4*)&As[k][tm];
            const unsigned long long* bp = (const unsigned long long*)&Bs[k][tn];
            unsigned long long b0 = bp[0], b1 = bp[1];
            unsigned long long a0 = dup2(av.x), a1 = dup2(av.y);
            unsigned long long a2 = dup2(av.z), a3 = dup2(av.w);
            acc[0][0] = fma2(a0, b0, acc[0][0]); acc[0][1] = fma2(a0, b1, acc[0][1]);
            acc[1][0] = fma2(a1, b0, acc[1][0]); acc[1][1] = fma2(a1, b1, acc[1][1]);
            acc[2][0] = fma2(a2, b0, acc[2][0]); acc[2][1] = fma2(a2, b1, acc[2][1]);
            acc[3][0] = fma2(a3, b0, acc[3][0]); acc[3][1] = fma2(a3, b1, acc[3][1]);
        }
    }

#pragma unroll
    for (int i = 0; i < 4; ++i) {
        float c0, c1, c2, c3;
        unpack2(acc[i][0], c0, c1);
        unpack2(acc[i][1], c2, c3);
        float4 o4 = {c0, c1, c2, c3};
        *(float4*)(S + (size_t)(bm + tm + i) * 2048 + bn + tn) = o4;
    }
}

// ============================================================
// Softmax over the 8 head planes (pointwise per (n,m), float4 lanes).
// Grid: 2048*2048/4/256 = 4096
// ============================================================
__global__ __launch_bounds__(256) void softmax8(float* __restrict__ P)
{
    const size_t idx = (size_t)blockIdx.x * 256 + threadIdx.x;  // float4 index
    const float scale = 0.08838834764831845f;                   // 1/sqrt(128)
    float4* P4 = (float4*)P;
    const size_t plane4 = (size_t)1 << 20;

    float4 v[8];
#pragma unroll
    for (int h = 0; h < 8; ++h) v[h] = P4[h * plane4 + idx];

#pragma unroll
    for (int lane = 0; lane < 4; ++lane) {
        float s[8], mx = -1e30f;
#pragma unroll
        for (int h = 0; h < 8; ++h) {
            s[h] = ((float*)&v[h])[lane] * scale;
            mx = fmaxf(mx, s[h]);
        }
        float sum = 0.f;
#pragma unroll
        for (int h = 0; h < 8; ++h) { s[h] = expf(s[h] - mx); sum += s[h]; }
        const float inv = 1.0f / sum;
#pragma unroll
        for (int h = 0; h < 8; ++h) ((float*)&v[h])[lane] = s[h] * inv;
    }

#pragma unroll
    for (int h = 0; h < 8; ++h) P4[h * plane4 + idx] = v[h];
}

// ============================================================
// Per-head attention GEMM (NN): attn[n,h*128+d] = sum_m P_h[n][m]*V[m,h*128+d]
// Grid: (2, 32, 8)
// ============================================================
__global__ __launch_bounds__(256) void attn_gemm(
    const float* __restrict__ P, const float* __restrict__ V,
    float* __restrict__ C)
{
    const int h = blockIdx.z;
    const float* A  = P + ((size_t)h << 22);
    const float* B  = V + h * 128;
    float*       Cc = C + h * 128;

    __shared__ float As[16][64];
    __shared__ float Bs[16][64];
    const int bm = blockIdx.y * 64;
    const int bn = blockIdx.x * 64;
    const int tid = threadIdx.x;
    const int lrA = tid >> 2;
    const int lcA = (tid & 3) << 2;
    const int krB = tid >> 4;
    const int cB  = (tid & 15) << 2;
    const int tm = (tid >> 4) << 2;
    const int tn = (tid & 15) << 2;

    unsigned long long acc[4][2];
#pragma unroll
    for (int i = 0; i < 4; ++i) { acc[i][0] = 0ull; acc[i][1] = 0ull; }

    for (int k0 = 0; k0 < 2048; k0 += 16) {
        float4 a = *(const float4*)(A + (size_t)(bm + lrA) * 2048 + k0 + lcA);
        float4 b = *(const float4*)(B + (size_t)(k0 + krB) * 1024 + bn + cB);
        __syncthreads();
        As[lcA + 0][lrA] = a.x; As[lcA + 1][lrA] = a.y;
        As[lcA + 2][lrA] = a.z; As[lcA + 3][lrA] = a.w;
        *(float4*)&Bs[krB][cB] = b;
        __syncthreads();
#pragma unroll
        for (int k = 0; k < 16; ++k) {
            float4 av = *(const float4*)&As[k][tm];
            const unsigned long long* bp = (const unsigned long long*)&Bs[k][tn];
            unsigned long long b0 = bp[0], b1 = bp[1];
            unsigned long long a0 = dup2(av.x), a1 = dup2(av.y);
            unsigned long long a2 = dup2(av.z), a3 = dup2(av.w);
            acc[0][0] = fma2(a0, b0, acc[0][0]); acc[0][1] = fma2(a0, b1, acc[0][1]);
            acc[1][0] = fma2(a1, b0, acc[1][0]); acc[1][1] = fma2(a1, b1, acc[1][1]);
            acc[2][0] = fma2(a2, b0, acc[2][0]); acc[2][1] = fma2(a2, b1, acc[2][1]);
            acc[3][0] = fma2(a3, b0, acc[3][0]); acc[3][1] = fma2(a3, b1, acc[3][1]);
        }
    }

#pragma unroll
    for (int i = 0; i < 4; ++i) {
        float c0, c1, c2, c3;
        unpack2(acc[i][0], c0, c1);
        unpack2(acc[i][1], c2, c3);
        float4 o4 = {c0, c1, c2, c3};
        *(float4*)(Cc + (size_t)(bm + tm + i) * 1024 + bn + tn) = o4;
    }
}

// ============================================================
// Residual + LayerNorm: Y = LN(X + R) * g + b, row length 1024.
// ============================================================
__global__ __launch_bounds__(256) void resid_ln(
    const float* __restrict__ X, const float* __restrict__ R,
    const float* __restrict__ g, const float* __restrict__ b,
    float* __restrict__ Y)
{
    __shared__ float red[8];
    const int row = blockIdx.x;
    const int tid = threadIdx.x;

    float4 xv = ((const float4*)(X + (size_t)row * 1024))[tid];
    float4 rv = ((const float4*)(R + (size_t)row * 1024))[tid];
    float v[4] = {xv.x + rv.x, xv.y + rv.y, xv.z + rv.z, xv.w + rv.w};

    float s = v[0] + v[1] + v[2] + v[3];
#pragma unroll
    for (int o = 16; o; o >>= 1) s += __shfl_xor_sync(0xffffffffu, s, o);
    if ((tid & 31) == 0) red[tid >> 5] = s;
    __syncthreads();
    float mean = 0.f;
#pragma unroll
    for (int w = 0; w < 8; ++w) mean += red[w];
    mean *= (1.0f / 1024.0f);

    float d0 = v[0] - mean, d1 = v[1] - mean, d2 = v[2] - mean, d3 = v[3] - mean;
    float ss = d0 * d0 + d1 * d1 + d2 * d2 + d3 * d3;
#pragma unroll
    for (int o = 16; o; o >>= 1) ss += __shfl_xor_sync(0xffffffffu, ss, o);
    __syncthreads();
    if ((tid & 31) == 0) red[tid >> 5] = ss;
    __syncthreads();
    float var = 0.f;
#pragma unroll
    for (int w = 0; w < 8; ++w) var += red[w];
    var *= (1.0f / 1024.0f);
    const float rstd = rsqrtf(var + 1e-5f);

    float4 gv = ((const float4*)g)[tid];
    float4 bv = ((const float4*)b)[tid];
    float4 o4;
    o4.x = d0 * rstd * gv.x + bv.x;
    o4.y = d1 * rstd * gv.y + bv.y;
    o4.z = d2 * rstd * gv.z + bv.z;
    o4.w = d3 * rstd * gv.w + bv.w;
    ((float4*)(Y + (size_t)row * 1024))[tid] = o4;
}

// ============================================================
extern "C" void kernel_launch(void* const* d_in, const int* in_sizes, int n_in,
                              void* d_out, int out_size)
{
    (void)in_sizes; (void)n_in; (void)out_size;
    const float* x1  = (const float*)d_in[0];
    const float* x2  = (const float*)d_in[1];
    const float* Wq  = (const float*)d_in[2];
    const float* bq  = (const float*)d_in[3];
    const float* Wk  = (const float*)d_in[4];
    const float* bk  = (const float*)d_in[5];
    const float* Wv  = (const float*)d_in[6];
    const float* bv  = (const float*)d_in[7];
    const float* Wo  = (const float*)d_in[8];
    const float* bo  = (const float*)d_in[9];
    const float* W1  = (const float*)d_in[10];
    const float* b1  = (const float*)d_in[11];
    const float* W2  = (const float*)d_in[12];
    const float* b2  = (const float*)d_in[13];
    const float* g1  = (const float*)d_in[14];
    const float* be1 = (const float*)d_in[15];
    const float* g2  = (const float*)d_in[16];
    const float* be2 = (const float*)d_in[17];
    float* out = (float*)d_out;

    float *Q, *K, *V, *P, *attn, *hb, *f1, *f2;
    cudaGetSymbolAddress((void**)&Q,    g_Q);
    cudaGetSymbolAddress((void**)&K,    g_K);
    cudaGetSymbolAddress((void**)&V,    g_V);
    cudaGetSymbolAddress((void**)&P,    g_P);
    cudaGetSymbolAddress((void**)&attn, g_attn);
    cudaGetSymbolAddress((void**)&hb,   g_h);
    cudaGetSymbolAddress((void**)&f1,   g_f1);
    cudaGetSymbolAddress((void**)&f2,   g_f2);

    dim3 t(256);

    // QKV projections
    gemm_nt<<<dim3(16, 32), t>>>(x1, Wq, bq, Q, 1024, 1024, 0);
    gemm_nt<<<dim3(16, 32), t>>>(x2, Wk, bk, K, 1024, 1024, 0);
    gemm_nt<<<dim3(16, 32), t>>>(x2, Wv, bv, V, 1024, 1024, 0);

    // per-head raw scores, then softmax over heads
    scores_gemm<<<dim3(32, 32, 8), t>>>(Q, K, P);
    softmax8<<<4096, t>>>(P);

    // attn = P_h @ V_h per head
    attn_gemm<<<dim3(2, 32, 8), t>>>(P, V, attn);

    // output projection (into f2 as temp)
    gemm_nt<<<dim3(16, 32), t>>>(attn, Wo, bo, f2, 1024, 1024, 0);

    // h = LN(x1 + attnproj)
    resid_ln<<<2048, t>>>(f2, x1, g1, be1, hb);

    // FFN
    gemm_nt<<<dim3(64, 32), t>>>(hb, W1, b1, f1, 4096, 1024, 1);
    gemm_nt<<<dim3(16, 32), t>>>(f1, W2, b2, f2, 1024, 4096, 0);

    // out = LN(h + ffn)
    resid_ln<<<2048, t>>>(f2, hb, g2, be2, out);
}

// round 3
// speedup vs baseline: 1.3475x; 1.1470x over previous
#include <cuda_runtime.h>
#include <math.h>

#define E_   1024
#define NH_  8
#define HD_  128
#define BS_  2048

typedef unsigned long long ULL;

// ---- scratch (device globals: no allocation allowed) ----
__device__ float g_Q[BS_ * E_];
__device__ float g_K[BS_ * E_];
__device__ float g_V[BS_ * E_];
__device__ float g_P[(size_t)NH_ * BS_ * BS_];   // 8 x 2048 x 2048 score/prob planes
__device__ float g_attn[BS_ * E_];
__device__ float g_h[BS_ * E_];
__device__ float g_f1[BS_ * 4 * E_];
__device__ float g_f2[BS_ * E_];
__device__ float g_zb[4 * E_];                   // zero bias (device globals are zero-init)

// ---- packed f32x2 helpers (SASS FFMA2; PTX-only path) ----
__device__ __forceinline__ ULL fma2(ULL a, ULL b, ULL c) {
    ULL d;
    asm("fma.rn.f32x2 %0, %1, %2, %3;" : "=l"(d) : "l"(a), "l"(b), "l"(c));
    return d;
}
__device__ __forceinline__ ULL dup2(float x) {
    ULL d;
    asm("mov.b64 %0, {%1, %1};" : "=l"(d) : "f"(x));
    return d;
}
__device__ __forceinline__ void unpack2(ULL p, float& lo, float& hi) {
    asm("mov.b64 {%0, %1}, %2;" : "=f"(lo), "=f"(hi) : "l"(p));
}

// ---- shared 8x8 micro-tile FMA step ----
__device__ __forceinline__ void micro_step(
    const float (*As)[128], const float (*Bs)[128],
    int k, int rm, int cn, ULL acc[8][4])
{
    float4 a0 = *(const float4*)&As[k][rm];
    float4 a1 = *(const float4*)&As[k][rm + 64];
    const ULL* bp0 = (const ULL*)&Bs[k][cn];
    const ULL* bp1 = (const ULL*)&Bs[k][cn + 64];
    ULL b0 = bp0[0], b1 = bp0[1], b2 = bp1[0], b3 = bp1[1];
    float am[8] = {a0.x, a0.y, a0.z, a0.w, a1.x, a1.y, a1.z, a1.w};
#pragma unroll
    for (int i = 0; i < 8; ++i) {
        ULL ai = dup2(am[i]);
        acc[i][0] = fma2(ai, b0, acc[i][0]);
        acc[i][1] = fma2(ai, b1, acc[i][1]);
        acc[i][2] = fma2(ai, b2, acc[i][2]);
        acc[i][3] = fma2(ai, b3, acc[i][3]);
    }
}

__device__ __forceinline__ void epilogue(
    ULL acc[8][4], const float* __restrict__ bias,
    float* __restrict__ C, size_t ldc,
    int bm, int bn, int rm, int cn, int relu)
{
    float4 bia0, bia1;
    bia0 = *(const float4*)(bias + bn + cn);
    bia1 = *(const float4*)(bias + bn + cn + 64);
#pragma unroll
    for (int i = 0; i < 8; ++i) {
        const int row = bm + rm + (i < 4 ? i : 64 + i - 4);
        float c0, c1, c2, c3, c4, c5, c6, c7;
        unpack2(acc[i][0], c0, c1); unpack2(acc[i][1], c2, c3);
        unpack2(acc[i][2], c4, c5); unpack2(acc[i][3], c6, c7);
        float4 o0 = {c0 + bia0.x, c1 + bia0.y, c2 + bia0.z, c3 + bia0.w};
        float4 o1 = {c4 + bia1.x, c5 + bia1.y, c6 + bia1.z, c7 + bia1.w};
        if (relu) {
            o0.x = fmaxf(o0.x, 0.f); o0.y = fmaxf(o0.y, 0.f);
            o0.z = fmaxf(o0.z, 0.f); o0.w = fmaxf(o0.w, 0.f);
            o1.x = fmaxf(o1.x, 0.f); o1.y = fmaxf(o1.y, 0.f);
            o1.z = fmaxf(o1.z, 0.f); o1.w = fmaxf(o1.w, 0.f);
        }
        *(float4*)(C + (size_t)row * ldc + bn + cn)      = o0;
        *(float4*)(C + (size_t)row * ldc + bn + cn + 64) = o1;
    }
}

// ============================================================
// NT GEMM: C[M,N] = A[M,K] @ W[N,K]^T + bias, opt ReLU
// BM=BN=128, BK=8, 256 threads, 8x8 micro-tile (split 4+4).
// Grid: (N/128, M/128)
// ============================================================
__global__ __launch_bounds__(256) void gemm_nt128(
    const float* __restrict__ A, size_t lda,
    const float* __restrict__ W, size_t ldb,
    const float* __restrict__ bias,
    float* __restrict__ C, size_t ldc,
    int K, int relu)
{
    __shared__ float As[8][128];
    __shared__ float Bs[8][128];
    const int bm = blockIdx.y * 128;
    const int bn = blockIdx.x * 128;
    const int tid = threadIdx.x;
    const int lr = tid >> 1;          // 0..127
    const int lc = (tid & 1) << 2;    // 0 or 4
    const int rm = (tid >> 4) << 2;   // 0..60
    const int cn = (tid & 15) << 2;   // 0..60

    ULL acc[8][4];
#pragma unroll
    for (int i = 0; i < 8; ++i)
#pragma unroll
        for (int j = 0; j < 4; ++j) acc[i][j] = 0ull;

    const float* pA = A + (size_t)(bm + lr) * lda + lc;
    const float* pB = W + (size_t)(bn + lr) * ldb + lc;

    for (int k0 = 0; k0 < K; k0 += 8) {
        float4 a = *(const float4*)(pA + k0);
        float4 b = *(const float4*)(pB + k0);
        __syncthreads();
        As[lc + 0][lr] = a.x; As[lc + 1][lr] = a.y;
        As[lc + 2][lr] = a.z; As[lc + 3][lr] = a.w;
        Bs[lc + 0][lr] = b.x; Bs[lc + 1][lr] = b.y;
        Bs[lc + 2][lr] = b.z; Bs[lc + 3][lr] = b.w;
        __syncthreads();
#pragma unroll
        for (int k = 0; k < 8; ++k) micro_step(As, Bs, k, rm, cn, acc);
    }

    epilogue(acc, bias, C, ldc, bm, bn, rm, cn, relu);
}

// ============================================================
// Per-head scores GEMM (NT): S_h[n,m] = sum_d Q[n,h*128+d]*K[m,h*128+d]
// Raw scores (scale folded into softmax). Grid: (16, 16, 8)
// ============================================================
__global__ __launch_bounds__(256) void scores128(
    const float* __restrict__ Q, const float* __restrict__ Kmat,
    float* __restrict__ P)
{
    const int h = blockIdx.z;
    const float* A = Q    + h * 128;
    const float* B = Kmat + h * 128;
    float*       S = P + ((size_t)h << 22);

    __shared__ float As[8][128];
    __shared__ float Bs[8][128];
    const int bm = blockIdx.y * 128;
    const int bn = blockIdx.x * 128;
    const int tid = threadIdx.x;
    const int lr = tid >> 1;
    const int lc = (tid & 1) << 2;
    const int rm = (tid >> 4) << 2;
    const int cn = (tid & 15) << 2;

    ULL acc[8][4];
#pragma unroll
    for (int i = 0; i < 8; ++i)
#pragma unroll
        for (int j = 0; j < 4; ++j) acc[i][j] = 0ull;

    const float* pA = A + (size_t)(bm + lr) * 1024 + lc;
    const float* pB = B + (size_t)(bn + lr) * 1024 + lc;

    for (int k0 = 0; k0 < 128; k0 += 8) {
        float4 a = *(const float4*)(pA + k0);
        float4 b = *(const float4*)(pB + k0);
        __syncthreads();
        As[lc + 0][lr] = a.x; As[lc + 1][lr] = a.y;
        As[lc + 2][lr] = a.z; As[lc + 3][lr] = a.w;
        Bs[lc + 0][lr] = b.x; Bs[lc + 1][lr] = b.y;
        Bs[lc + 2][lr] = b.z; Bs[lc + 3][lr] = b.w;
        __syncthreads();
#pragma unroll
        for (int k = 0; k < 8; ++k) micro_step(As, Bs, k, rm, cn, acc);
    }

#pragma unroll
    for (int i = 0; i < 8; ++i) {
        const int row = bm + rm + (i < 4 ? i : 64 + i - 4);
        float c0, c1, c2, c3, c4, c5, c6, c7;
        unpack2(acc[i][0], c0, c1); unpack2(acc[i][1], c2, c3);
        unpack2(acc[i][2], c4, c5); unpack2(acc[i][3], c6, c7);
        float4 o0 = {c0, c1, c2, c3};
        float4 o1 = {c4, c5, c6, c7};
        *(float4*)(S + (size_t)row * 2048 + bn + cn)      = o0;
        *(float4*)(S + (size_t)row * 2048 + bn + cn + 64) = o1;
    }
}

// ============================================================
// Per-head attention GEMM (NN): attn[n,h*128+d] = sum_m P_h[n][m]*V[m,h*128+d]
// BN=128 covers full head dim. Grid: (1, 16, 8)
// ============================================================
__global__ __launch_bounds__(256) void attn128(
    const float* __restrict__ P, const float* __restrict__ V,
    float* __restrict__ C)
{
    const int h = blockIdx.z;
    const float* A  = P + ((size_t)h << 22);
    const float* B  = V + h * 128;
    float*       Cc = C + h * 128;

    __shared__ float As[8][128];
    __shared__ float Bs[8][128];
    const int bm = blockIdx.y * 128;
    const int tid = threadIdx.x;
    const int lr = tid >> 1;          // A loader: 0..127
    const int lc = (tid & 1) << 2;
    const int kr = tid >> 5;          // B loader k-row: 0..7
    const int nc = (tid & 31) << 2;   // B loader col: 0..124
    const int rm = (tid >> 4) << 2;
    const int cn = (tid & 15) << 2;

    ULL acc[8][4];
#pragma unroll
    for (int i = 0; i < 8; ++i)
#pragma unroll
        for (int j = 0; j < 4; ++j) acc[i][j] = 0ull;

    const float* pA = A + (size_t)(bm + lr) * 2048 + lc;

    for (int k0 = 0; k0 < 2048; k0 += 8) {
        float4 a = *(const float4*)(pA + k0);
        float4 b = *(const float4*)(B + (size_t)(k0 + kr) * 1024 + nc);
        __syncthreads();
        As[lc + 0][lr] = a.x; As[lc + 1][lr] = a.y;
        As[lc + 2][lr] = a.z; As[lc + 3][lr] = a.w;
        *(float4*)&Bs[kr][nc] = b;
        __syncthreads();
#pragma unroll
        for (int k = 0; k < 8; ++k) micro_step(As, Bs, k, rm, cn, acc);
    }

#pragma unroll
    for (int i = 0; i < 8; ++i) {
        const int row = bm + rm + (i < 4 ? i : 64 + i - 4);
        float c0, c1, c2, c3, c4, c5, c6, c7;
        unpack2(acc[i][0], c0, c1); unpack2(acc[i][1], c2, c3);
        unpack2(acc[i][2], c4, c5); unpack2(acc[i][3], c6, c7);
        float4 o0 = {c0, c1, c2, c3};
        float4 o1 = {c4, c5, c6, c7};
        *(float4*)(Cc + (size_t)row * 1024 + cn)      = o0;
        *(float4*)(Cc + (size_t)row * 1024 + cn + 64) = o1;
    }
}

// ============================================================
// Softmax over the 8 head planes (pointwise per (n,m), float4 lanes).
// Grid: 2048*2048/4/256 = 4096
// ============================================================
__global__ __launch_bounds__(256) void softmax8(float* __restrict__ P)
{
    const size_t idx = (size_t)blockIdx.x * 256 + threadIdx.x;  // float4 index
    const float scale = 0.08838834764831845f;                   // 1/sqrt(128)
    float4* P4 = (float4*)P;
    const size_t plane4 = (size_t)1 << 20;

    float4 v[8];
#pragma unroll
    for (int h = 0; h < 8; ++h) v[h] = P4[h * plane4 + idx];

#pragma unroll
    for (int lane = 0; lane < 4; ++lane) {
        float s[8], mx = -1e30f;
#pragma unroll
        for (int h = 0; h < 8; ++h) {
            s[h] = ((float*)&v[h])[lane] * scale;
            mx = fmaxf(mx, s[h]);
        }
        float sum = 0.f;
#pragma unroll
        for (int h = 0; h < 8; ++h) { s[h] = expf(s[h] - mx); sum += s[h]; }
        const float inv = 1.0f / sum;
#pragma unroll
        for (int h = 0; h < 8; ++h) ((float*)&v[h])[lane] = s[h] * inv;
    }

#pragma unroll
    for (int h = 0; h < 8; ++h) P4[h * plane4 + idx] = v[h];
}

// ============================================================
// Residual + LayerNorm: Y = LN(X + R) * g + b, row length 1024.
// ============================================================
__global__ __launch_bounds__(256) void resid_ln(
    const float* __restrict__ X, const float* __restrict__ R,
    const float* __restrict__ g, const float* __restrict__ b,
    float* __restrict__ Y)
{
    __shared__ float red[8];
    const int row = blockIdx.x;
    const int tid = threadIdx.x;

    float4 xv = ((const float4*)(X + (size_t)row * 1024))[tid];
    float4 rv = ((const float4*)(R + (size_t)row * 1024))[tid];
    float v[4] = {xv.x + rv.x, xv.y + rv.y, xv.z + rv.z, xv.w + rv.w};

    float s = v[0] + v[1] + v[2] + v[3];
#pragma unroll
    for (int o = 16; o; o >>= 1) s += __shfl_xor_sync(0xffffffffu, s, o);
    if ((tid & 31) == 0) red[tid >> 5] = s;
    __syncthreads();
    float mean = 0.f;
#pragma unroll
    for (int w = 0; w < 8; ++w) mean += red[w];
    mean *= (1.0f / 1024.0f);

    float d0 = v[0] - mean, d1 = v[1] - mean, d2 = v[2] - mean, d3 = v[3] - mean;
    float ss = d0 * d0 + d1 * d1 + d2 * d2 + d3 * d3;
#pragma unroll
    for (int o = 16; o; o >>= 1) ss += __shfl_xor_sync(0xffffffffu, ss, o);
    __syncthreads();
    if ((tid & 31) == 0) red[tid >> 5] = ss;
    __syncthreads();
    float var = 0.f;
#pragma unroll
    for (int w = 0; w < 8; ++w) var += red[w];
    var *= (1.0f / 1024.0f);
    const float rstd = rsqrtf(var + 1e-5f);

    float4 gv = ((const float4*)g)[tid];
    float4 bv = ((const float4*)b)[tid];
    float4 o4;
    o4.x = d0 * rstd * gv.x + bv.x;
    o4.y = d1 * rstd * gv.y + bv.y;
    o4.z = d2 * rstd * gv.z + bv.z;
    o4.w = d3 * rstd * gv.w + bv.w;
    ((float4*)(Y + (size_t)row * 1024))[tid] = o4;
}

// ============================================================
extern "C" void kernel_launch(void* const* d_in, const int* in_sizes, int n_in,
                              void* d_out, int out_size)
{
    (void)in_sizes; (void)n_in; (void)out_size;
    const float* x1  = (const float*)d_in[0];
    const float* x2  = (const float*)d_in[1];
    const float* Wq  = (const float*)d_in[2];
    const float* bq  = (const float*)d_in[3];
    const float* Wk  = (const float*)d_in[4];
    const float* bk  = (const float*)d_in[5];
    const float* Wv  = (const float*)d_in[6];
    const float* bv  = (const float*)d_in[7];
    const float* Wo  = (const float*)d_in[8];
    const float* bo  = (const float*)d_in[9];
    const float* W1  = (const float*)d_in[10];
    const float* b1  = (const float*)d_in[11];
    const float* W2  = (const float*)d_in[12];
    const float* b2  = (const float*)d_in[13];
    const float* g1  = (const float*)d_in[14];
    const float* be1 = (const float*)d_in[15];
    const float* g2  = (const float*)d_in[16];
    const float* be2 = (const float*)d_in[17];
    float* out = (float*)d_out;

    float *Q, *K, *V, *P, *attn, *hb, *f1, *f2;
    cudaGetSymbolAddress((void**)&Q,    g_Q);
    cudaGetSymbolAddress((void**)&K,    g_K);
    cudaGetSymbolAddress((void**)&V,    g_V);
    cudaGetSymbolAddress((void**)&P,    g_P);
    cudaGetSymbolAddress((void**)&attn, g_attn);
    cudaGetSymbolAddress((void**)&hb,   g_h);
    cudaGetSymbolAddress((void**)&f1,   g_f1);
    cudaGetSymbolAddress((void**)&f2,   g_f2);

    dim3 t(256);

    // QKV projections: M=2048, N=1024, K=1024
    gemm_nt128<<<dim3(8, 16), t>>>(x1, 1024, Wq, 1024, bq, Q, 1024, 1024, 0);
    gemm_nt128<<<dim3(8, 16), t>>>(x2, 1024, Wk, 1024, bk, K, 1024, 1024, 0);
    gemm_nt128<<<dim3(8, 16), t>>>(x2, 1024, Wv, 1024, bv, V, 1024, 1024, 0);

    // per-head raw scores, then softmax over heads
    scores128<<<dim3(16, 16, 8), t>>>(Q, K, P);
    softmax8<<<4096, t>>>(P);

    // attn = P_h @ V_h per head
    attn128<<<dim3(1, 16, 8), t>>>(P, V, attn);

    // output projection (into f2 as temp)
    gemm_nt128<<<dim3(8, 16), t>>>(attn, 1024, Wo, 1024, bo, f2, 1024, 1024, 0);

    // h = LN(x1 + attnproj)
    resid_ln<<<2048, t>>>(f2, x1, g1, be1, hb);

    // FFN: [2048,1024] @ W1[4096,1024]^T -> relu -> @ W2[1024,4096]^T
    gemm_nt128<<<dim3(32, 16), t>>>(hb, 1024, W1, 1024, b1, f1, 4096, 1024, 1);
    gemm_nt128<<<dim3(8, 16), t>>>(f1, 4096, W2, 4096, b2, f2, 1024, 4096, 0);

    // out = LN(h + ffn)
    resid_ln<<<2048, t>>>(f2, hb, g2, be2, out);
}

// round 8
// speedup vs baseline: 3.3214x; 2.4650x over previous
#include <cuda_runtime.h>
#include <math.h>
#include <stdint.h>

#define E_   1024
#define NH_  8
#define HD_  128
#define BS_  2048

// ---- scratch (device globals: no allocation allowed) ----
__device__ float g_Q[BS_ * E_];
__device__ float g_K[BS_ * E_];
__device__ float g_V[BS_ * E_];
__device__ float g_Vt[NH_ * HD_ * BS_];          // per-head transposed V: [h][d][m]
__device__ float g_P[(size_t)NH_ * BS_ * BS_];   // 8 x 2048 x 2048 score/prob planes
__device__ float g_attn[BS_ * E_];
__device__ float g_h[BS_ * E_];
__device__ float g_f1[BS_ * 4 * E_];
__device__ float g_f2[BS_ * E_];
__device__ float g_zb[4 * E_];                   // zero bias (zero-initialized)

// ============================================================
// helpers: cp.async + tf32 mma.sync (base sm_103 ISA, no "a" features)
// ============================================================
__device__ __forceinline__ uint32_t smem_u32(const void* p) {
    uint32_t a;
    asm("{ .reg .u64 t; cvta.to.shared.u64 t, %1; cvt.u32.u64 %0, t; }" : "=r"(a) : "l"(p));
    return a;
}
__device__ __forceinline__ void cp16(uint32_t dst, const void* src) {
    asm volatile("cp.async.cg.shared.global [%0], [%1], 16;" :: "r"(dst), "l"(src));
}
#define CP_COMMIT() asm volatile("cp.async.commit_group;" ::: "memory")
#define CP_WAIT2()  asm volatile("cp.async.wait_group 2;" ::: "memory")

__device__ __forceinline__ uint32_t to_tf32(float f) {
    uint32_t r;
    asm("cvt.rna.tf32.f32 %0, %1;" : "=r"(r) : "f"(f));
    return r;
}
__device__ __forceinline__ void mma8(float c[4], uint32_t a0, uint32_t a1,
                                     uint32_t a2, uint32_t a3,
                                     uint32_t b0, uint32_t b1) {
    asm volatile(
        "mma.sync.aligned.m16n8k8.row.col.f32.tf32.tf32.f32 "
        "{%0,%1,%2,%3}, {%4,%5,%6,%7}, {%8,%9}, {%0,%1,%2,%3};"
        : "+f"(c[0]), "+f"(c[1]), "+f"(c[2]), "+f"(c[3])
        : "r"(a0), "r"(a1), "r"(a2), "r"(a3), "r"(b0), "r"(b1));
}

// ============================================================
// Unified tf32 tensor-core NT GEMM: C = A @ B^T + bias, opt ReLU
// BM=BN=128, BK=32, 3-stage cp.async pipeline, 8 warps (2x4),
// warp tile 64x32, mma m16n8k8. Grid: (N/128, M/128, Z).
// Per-z pointer offsets az/bz/cz handle head planes / column slices.
// ============================================================
#define SROW 36                       // padded row stride (floats)
#define STAGE_F (2 * 128 * SROW)      // floats per stage (A tile + B tile)
#define GEMM_SMEM (3 * STAGE_F * 4)   // bytes

__global__ __launch_bounds__(256, 1) void gemm_mma(
    const float* __restrict__ A, long long az, int lda,
    const float* __restrict__ B, long long bz, int ldb,
    const float* __restrict__ bias,
    float* __restrict__ C, long long cz, int ldc,
    int K, int relu)
{
    extern __shared__ __align__(16) float sm[];
    const int tid = threadIdx.x;
    const int bm = blockIdx.y * 128, bn = blockIdx.x * 128;
    A += (size_t)blockIdx.z * az;
    B += (size_t)blockIdx.z * bz;
    C += (size_t)blockIdx.z * cz;

    // loader mapping: each thread owns one 64B chunk of one row (A and B)
    const int lrow = tid >> 1;            // 0..127
    const int lhalf = (tid & 1) << 4;     // 0 or 16 floats
    const float* gA = A + (size_t)(bm + lrow) * lda + lhalf;
    const float* gB = B + (size_t)(bn + lrow) * ldb + lhalf;
    const uint32_t sA0 = smem_u32(sm) + (uint32_t)(lrow * SROW + lhalf) * 4u;
    const uint32_t sB0 = sA0 + 128u * SROW * 4u;

    // compute mapping
    const int warp = tid >> 5, lane = tid & 31;
    const int g = lane >> 2, tig = lane & 3;
    const int am = (warp >> 2) * 64;      // warp M offset (0 or 64)
    const int bnw = (warp & 3) * 32;      // warp N offset (0..96)

    float acc[4][4][4];
#pragma unroll
    for (int mi = 0; mi < 4; ++mi)
#pragma unroll
        for (int ni = 0; ni < 4; ++ni)
#pragma unroll
            for (int r = 0; r < 4; ++r) acc[mi][ni][r] = 0.f;

    const int NT = K >> 5;

    // prologue: stages 0,1
#pragma unroll
    for (int s = 0; s < 2; ++s) {
        const uint32_t dA = sA0 + (uint32_t)(s * STAGE_F) * 4u;
        const uint32_t dB = sB0 + (uint32_t)(s * STAGE_F) * 4u;
        const float* pa = gA + s * 32;
        const float* pb = gB + s * 32;
#pragma unroll
        for (int c = 0; c < 4; ++c) {
            cp16(dA + c * 16u, pa + c * 4);
            cp16(dB + c * 16u, pb + c * 4);
        }
        CP_COMMIT();
    }

    for (int kt = 0; kt < NT; ++kt) {
        if (kt + 2 < NT) {
            const int s = (kt + 2) % 3;
            const uint32_t dA = sA0 + (uint32_t)(s * STAGE_F) * 4u;
            const uint32_t dB = sB0 + (uint32_t)(s * STAGE_F) * 4u;
            const float* pa = gA + (kt + 2) * 32;
            const float* pb = gB + (kt + 2) * 32;
#pragma unroll
            for (int c = 0; c < 4; ++c) {
                cp16(dA + c * 16u, pa + c * 4);
                cp16(dB + c * 16u, pb + c * 4);
            }
        }
        CP_COMMIT();
        CP_WAIT2();
        __syncthreads();

        const float* As = sm + (kt % 3) * STAGE_F;
        const float* Bs = As + 128 * SROW;

#pragma unroll
        for (int k8 = 0; k8 < 4; ++k8) {
            const int kk = k8 * 8;
            uint32_t a[4][4];
#pragma unroll
            for (int mi = 0; mi < 4; ++mi) {
                const float* p = As + (am + mi * 16 + g) * SROW + kk + tig;
                a[mi][0] = to_tf32(p[0]);
                a[mi][2] = to_tf32(p[4]);
                a[mi][1] = to_tf32(p[8 * SROW]);
                a[mi][3] = to_tf32(p[8 * SROW + 4]);
            }
            uint32_t b[4][2];
#pragma unroll
            for (int ni = 0; ni < 4; ++ni) {
                const float* q = Bs + (bnw + ni * 8 + g) * SROW + kk + tig;
                b[ni][0] = to_tf32(q[0]);
                b[ni][1] = to_tf32(q[4]);
            }
#pragma unroll
            for (int mi = 0; mi < 4; ++mi)
#pragma unroll
                for (int ni = 0; ni < 4; ++ni)
                    mma8(acc[mi][ni], a[mi][0], a[mi][1], a[mi][2], a[mi][3],
                         b[ni][0], b[ni][1]);
        }
        __syncthreads();
    }

    // epilogue
#pragma unroll
    for (int mi = 0; mi < 4; ++mi) {
        const int r0 = bm + am + mi * 16 + g;
#pragma unroll
        for (int ni = 0; ni < 4; ++ni) {
            const int col = bn + bnw + ni * 8 + 2 * tig;
            const float bi0 = bias[col], bi1 = bias[col + 1];
            float v0 = acc[mi][ni][0] + bi0, v1 = acc[mi][ni][1] + bi1;
            float v2 = acc[mi][ni][2] + bi0, v3 = acc[mi][ni][3] + bi1;
            if (relu) {
                v0 = fmaxf(v0, 0.f); v1 = fmaxf(v1, 0.f);
                v2 = fmaxf(v2, 0.f); v3 = fmaxf(v3, 0.f);
            }
            float2 p0 = {v0, v1}, p1 = {v2, v3};
            *(float2*)(C + (size_t)r0 * ldc + col) = p0;
            *(float2*)(C + (size_t)(r0 + 8) * ldc + col) = p1;
        }
    }
}

// ============================================================
// V transpose: Vt[h][d][m] = V[m][h*128+d]. Grid (64,4,8), block (32,8)
// ============================================================
__global__ void vt_kernel(const float* __restrict__ V, float* __restrict__ Vt)
{
    __shared__ float t[32][33];
    const int m0 = blockIdx.x * 32, d0 = blockIdx.y * 32, h = blockIdx.z;
    const int tx = threadIdx.x, ty = threadIdx.y;
#pragma unroll
    for (int j = 0; j < 32; j += 8)
        t[ty + j][tx] = V[(size_t)(m0 + ty + j) * 1024 + h * 128 + d0 + tx];
    __syncthreads();
    float* dst = Vt + (size_t)h * 128 * 2048;
#pragma unroll
    for (int j = 0; j < 32; j += 8)
        dst[(size_t)(d0 + ty + j) * 2048 + m0 + tx] = t[tx][ty + j];
}

// ============================================================
// Softmax over the 8 head planes (pointwise per (n,m), float4 lanes).
// ============================================================
__global__ __launch_bounds__(256) void softmax8(float* __restrict__ P)
{
    const size_t idx = (size_t)blockIdx.x * 256 + threadIdx.x;
    const float scale = 0.08838834764831845f;  // 1/sqrt(128)
    float4* P4 = (float4*)P;
    const size_t plane4 = (size_t)1 << 20;

    float4 v[8];
#pragma unroll
    for (int h = 0; h < 8; ++h) v[h] = P4[h * plane4 + idx];

#pragma unroll
    for (int lane = 0; lane < 4; ++lane) {
        float s[8], mx = -1e30f;
#pragma unroll
        for (int h = 0; h < 8; ++h) {
            s[h] = ((float*)&v[h])[lane] * scale;
            mx = fmaxf(mx, s[h]);
        }
        float sum = 0.f;
#pragma unroll
        for (int h = 0; h < 8; ++h) { s[h] = expf(s[h] - mx); sum += s[h]; }
        const float inv = 1.0f / sum;
#pragma unroll
        for (int h = 0; h < 8; ++h) ((float*)&v[h])[lane] = s[h] * inv;
    }

#pragma unroll
    for (int h = 0; h < 8; ++h) P4[h * plane4 + idx] = v[h];
}

// ============================================================
// Residual + LayerNorm: Y = LN(X + R) * g + b, row length 1024.
// ============================================================
__global__ __launch_bounds__(256) void resid_ln(
    const float* __restrict__ X, const float* __restrict__ R,
    const float* __restrict__ g, const float* __restrict__ b,
    float* __restrict__ Y)
{
    __shared__ float red[8];
    const int row = blockIdx.x;
    const int tid = threadIdx.x;

    float4 xv = ((const float4*)(X + (size_t)row * 1024))[tid];
    float4 rv = ((const float4*)(R + (size_t)row * 1024))[tid];
    float v[4] = {xv.x + rv.x, xv.y + rv.y, xv.z + rv.z, xv.w + rv.w};

    float s = v[0] + v[1] + v[2] + v[3];
#pragma unroll
    for (int o = 16; o; o >>= 1) s += __shfl_xor_sync(0xffffffffu, s, o);
    if ((tid & 31) == 0) red[tid >> 5] = s;
    __syncthreads();
    float mean = 0.f;
#pragma unroll
    for (int w = 0; w < 8; ++w) mean += red[w];
    mean *= (1.0f / 1024.0f);

    float d0 = v[0] - mean, d1 = v[1] - mean, d2 = v[2] - mean, d3 = v[3] - mean;
    float ss = d0 * d0 + d1 * d1 + d2 * d2 + d3 * d3;
#pragma unroll
    for (int o = 16; o; o >>= 1) ss += __shfl_xor_sync(0xffffffffu, ss, o);
    __syncthreads();
    if ((tid & 31) == 0) red[tid >> 5] = ss;
    __syncthreads();
    float var = 0.f;
#pragma unroll
    for (int w = 0; w < 8; ++w) var += red[w];
    var *= (1.0f / 1024.0f);
    const float rstd = rsqrtf(var + 1e-5f);

    float4 gv = ((const float4*)g)[tid];
    float4 bv = ((const float4*)b)[tid];
    float4 o4;
    o4.x = d0 * rstd * gv.x + bv.x;
    o4.y = d1 * rstd * gv.y + bv.y;
    o4.z = d2 * rstd * gv.z + bv.z;
    o4.w = d3 * rstd * gv.w + bv.w;
    ((float4*)(Y + (size_t)row * 1024))[tid] = o4;
}

// ============================================================
extern "C" void kernel_launch(void* const* d_in, const int* in_sizes, int n_in,
                              void* d_out, int out_size)
{
    (void)in_sizes; (void)n_in; (void)out_size;
    const float* x1  = (const float*)d_in[0];
    const float* x2  = (const float*)d_in[1];
    const float* Wq  = (const float*)d_in[2];
    const float* bq  = (const float*)d_in[3];
    const float* Wk  = (const float*)d_in[4];
    const float* bk  = (const float*)d_in[5];
    const float* Wv  = (const float*)d_in[6];
    const float* bv  = (const float*)d_in[7];
    const float* Wo  = (const float*)d_in[8];
    const float* bo  = (const float*)d_in[9];
    const float* W1  = (const float*)d_in[10];
    const float* b1  = (const float*)d_in[11];
    const float* W2  = (const float*)d_in[12];
    const float* b2  = (const float*)d_in[13];
    const float* g1  = (const float*)d_in[14];
    const float* be1 = (const float*)d_in[15];
    const float* g2  = (const float*)d_in[16];
    const float* be2 = (const float*)d_in[17];
    float* out = (float*)d_out;

    float *Q, *K, *V, *Vt, *P, *attn, *hb, *f1, *f2, *zb;
    cudaGetSymbolAddress((void**)&Q,    g_Q);
    cudaGetSymbolAddress((void**)&K,    g_K);
    cudaGetSymbolAddress((void**)&V,    g_V);
    cudaGetSymbolAddress((void**)&Vt,   g_Vt);
    cudaGetSymbolAddress((void**)&P,    g_P);
    cudaGetSymbolAddress((void**)&attn, g_attn);
    cudaGetSymbolAddress((void**)&hb,   g_h);
    cudaGetSymbolAddress((void**)&f1,   g_f1);
    cudaGetSymbolAddress((void**)&f2,   g_f2);
    cudaGetSymbolAddress((void**)&zb,   g_zb);

    cudaFuncSetAttribute(gemm_mma, cudaFuncAttributeMaxDynamicSharedMemorySize, GEMM_SMEM);

    dim3 t256(256);

    // QKV projections: M=2048, N=1024, K=1024
    gemm_mma<<<dim3(8, 16, 1), t256, GEMM_SMEM>>>(x1, 0, 1024, Wq, 0, 1024, bq, Q, 0, 1024, 1024, 0);
    gemm_mma<<<dim3(8, 16, 1), t256, GEMM_SMEM>>>(x2, 0, 1024, Wk, 0, 1024, bk, K, 0, 1024, 1024, 0);
    gemm_mma<<<dim3(8, 16, 1), t256, GEMM_SMEM>>>(x2, 0, 1024, Wv, 0, 1024, bv, V, 0, 1024, 1024, 0);

    // transpose V -> Vt[h][d][m]
    vt_kernel<<<dim3(64, 4, 8), dim3(32, 8)>>>(V, Vt);

    // scores per head: S_h = Q_h @ K_h^T (raw; scale folded into softmax)
    gemm_mma<<<dim3(16, 16, 8), t256, GEMM_SMEM>>>(Q, 128, 1024, K, 128, 1024, zb,
                                                   P, (long long)1 << 22, 2048, 128, 0);
    softmax8<<<4096, t256>>>(P);

    // attn: attn[:, h*128:(h+1)*128] = P_h @ Vt_h^T
    gemm_mma<<<dim3(1, 16, 8), t256, GEMM_SMEM>>>(P, (long long)1 << 22, 2048,
                                                  Vt, 128ll * 2048, 2048, zb,
                                                  attn, 128, 1024, 2048, 0);

    // output projection
    gemm_mma<<<dim3(8, 16, 1), t256, GEMM_SMEM>>>(attn, 0, 1024, Wo, 0, 1024, bo, f2, 0, 1024, 1024, 0);

    // h = LN(x1 + attnproj)
    resid_ln<<<2048, t256>>>(f2, x1, g1, be1, hb);

    // FFN
    gemm_mma<<<dim3(32, 16, 1), t256, GEMM_SMEM>>>(hb, 0, 1024, W1, 0, 1024, b1, f1, 0, 4096, 1024, 1);
    gemm_mma<<<dim3(8, 16, 1), t256, GEMM_SMEM>>>(f1, 0, 4096, W2, 0, 4096, b2, f2, 0, 1024, 4096, 0);

    // out = LN(h + ffn)
    resid_ln<<<2048, t256>>>(f2, hb, g2, be2, out);
}